// round 9
// baseline (speedup 1.0000x reference)
#include <cuda_runtime.h>
#include <cuda_fp16.h>
#include <cstdint>
#include <cstddef>

#define NB 1024
#define NT 512
#define NH 128
#define BT (NB * NT)

// ---------------- scratch (device globals; no runtime allocation) ----------------
__device__ __half g_h0[(size_t)NB * NT * NH];   // layer0 out fp16 [B][T][H]
__device__ __half g_h1[(size_t)NB * NT * NH];   // layer1 out fp16 [B][T][H]
__device__ float  g_hlast[NB * NH];             // layer2 last h (fp32)
__device__ float  g_xp[(size_t)BT * 512];       // x-projection (reused per layer)
__device__ __half g_WTh[3][64 * NH * 8];        // recurrent w_hh packed [kk][u][8]
__device__ __half g_WF[2][65536];               // mma frag-packed w_ih (layers 1,2)
__device__ float  g_biasxp[3][512];             // per-layer bias (c = u*4+q order)
__device__ float  g_w0p[512 * 8];               // layer0 w_ih packed [c][8] (k<6)

// ---------------- activations ----------------
__device__ __forceinline__ float fast_tanh(float x) {
    float y;
    asm("tanh.approx.f32 %0, %1;" : "=f"(y) : "f"(x));
    return y;
}
__device__ __forceinline__ float fast_sig(float x) {
    return fmaf(0.5f, fast_tanh(0.5f * x), 0.5f);
}
__device__ __forceinline__ uint32_t smem_u32(const void* p) {
    uint32_t a;
    asm("{ .reg .u64 t; cvta.to.shared.u64 t, %1; cvt.u32.u64 %0, t; }" : "=r"(a) : "l"(p));
    return a;
}

// ---------------- prep: recurrent w_hh pack ----------------
__global__ void prep_rec_kernel(const float* __restrict__ w_hh, __half* __restrict__ WT)
{
    for (int idx = blockIdx.x * blockDim.x + threadIdx.x; idx < 64 * NH * 8;
         idx += gridDim.x * blockDim.x) {
        int h8 = idx & 7;
        int u  = (idx >> 3) & 127;
        int kk = idx >> 10;
        int q = h8 >> 1, par = h8 & 1;
        int k = 2 * kk + par;
        WT[idx] = __float2half(w_hh[(q * NH + u) * NH + k]);
    }
}

// ---------------- prep: mma B-frag pack (layers 1,2) + bias ----------------
__global__ void prep_mma_kernel(const float* __restrict__ w_ih,
                                const float* __restrict__ b_ih,
                                const float* __restrict__ b_hh,
                                __half* __restrict__ WF, float* __restrict__ bias)
{
    for (int idx = blockIdx.x * blockDim.x + threadIdx.x; idx < 65536;
         idx += gridDim.x * blockDim.x) {
        int h4   = idx & 3;
        int lane = (idx >> 2) & 31;
        int ks   = (idx >> 7) & 7;
        int cb   = idx >> 10;
        int c = cb * 8 + (lane >> 2);
        int q = c & 3, u = c >> 2;
        int g = q * NH + u;
        int k = ks * 16 + (lane & 3) * 2 + (h4 & 1) + (h4 >> 1) * 8;
        WF[idx] = __float2half(w_ih[g * NH + k]);
    }
    for (int c = blockIdx.x * blockDim.x + threadIdx.x; c < 512;
         c += gridDim.x * blockDim.x) {
        int q = c & 3, u = c >> 2;
        int g = q * NH + u;
        bias[c] = b_ih[g] + b_hh[g];
    }
}

// ---------------- prep: layer0 w_ih pack (K=6) + bias ----------------
__global__ void prep_l0_kernel(const float* __restrict__ w_ih,
                               const float* __restrict__ b_ih,
                               const float* __restrict__ b_hh,
                               float* __restrict__ w0p, float* __restrict__ bias)
{
    for (int idx = blockIdx.x * blockDim.x + threadIdx.x; idx < 512 * 8;
         idx += gridDim.x * blockDim.x) {
        int k = idx & 7, c = idx >> 3;
        int q = c & 3, u = c >> 2;
        int g = q * NH + u;
        w0p[idx] = (k < 6) ? w_ih[g * 6 + k] : 0.0f;
    }
    for (int c = blockIdx.x * blockDim.x + threadIdx.x; c < 512;
         c += gridDim.x * blockDim.x) {
        int q = c & 3, u = c >> 2;
        int g = q * NH + u;
        bias[c] = b_ih[g] + b_hh[g];
    }
}

// ---------------- layer0 x-projection (scalar, K=6) ----------------
__global__ void __launch_bounds__(512, 1)
xp0_kernel(const float* __restrict__ x, const float* __restrict__ w0p,
           const float* __restrict__ bias, float* __restrict__ XP)
{
    __shared__ __align__(16) float xs[128 * 8];
    const int tid = threadIdx.x;
    const size_t row0 = (size_t)blockIdx.x * 128;

    for (int i = tid; i < 1024; i += 512) {
        int r = i >> 3, k = i & 7;
        xs[i] = (k < 6) ? x[(row0 + r) * 6 + k] : 0.0f;
    }
    __syncthreads();

    const int c = tid;
    float4 w01 = *reinterpret_cast<const float4*>(&w0p[c * 8]);
    float4 w23 = *reinterpret_cast<const float4*>(&w0p[c * 8 + 4]);
    float bc = bias[c];
    for (int r = 0; r < 128; ++r) {
        float4 x01 = *reinterpret_cast<const float4*>(&xs[r * 8]);
        float2 x2  = *reinterpret_cast<const float2*>(&xs[r * 8 + 4]);
        float s = bc;
        s = fmaf(w01.x, x01.x, s);
        s = fmaf(w01.y, x01.y, s);
        s = fmaf(w01.z, x01.z, s);
        s = fmaf(w01.w, x01.w, s);
        s = fmaf(w23.x, x2.x, s);
        s = fmaf(w23.y, x2.y, s);
        XP[(row0 + r) * 512 + c] = s;
    }
}

// ---------------- layers 1,2 x-projection via mma.sync ----------------
__global__ void __launch_bounds__(512, 1)
xp_mma_kernel(const __half* __restrict__ X, const __half* __restrict__ WF,
              const float* __restrict__ bias, float* __restrict__ XP)
{
    __shared__ __align__(16) __half xs[128 * 136];
    const int tid  = threadIdx.x;
    const int wid  = tid >> 5;
    const int lane = tid & 31;
    const size_t row0 = (size_t)blockIdx.x * 128;
    const int ny = blockIdx.y;

    for (int i = tid; i < 2048; i += 512) {
        int r = i >> 4, cvec = i & 15;
        reinterpret_cast<uint4*>(xs)[r * 17 + cvec] =
            reinterpret_cast<const uint4*>(X + (row0 + r) * NH)[cvec];
    }
    __syncthreads();

    const int wm = wid & 3;
    const int wn = wid >> 2;
    const int cb0 = ny * 32 + wn * 8;
    const uint2* __restrict__ WFp = reinterpret_cast<const uint2*>(WF);

    const int lrow = (lane & 7) + ((lane >> 3) & 1) * 8;
    const int kadd = (lane >> 4) * 8;
    const uint32_t xsb = smem_u32(xs);

    float acc[2][8][4];
#pragma unroll
    for (int mt = 0; mt < 2; ++mt)
#pragma unroll
        for (int nt = 0; nt < 8; ++nt)
#pragma unroll
            for (int i = 0; i < 4; ++i) acc[mt][nt][i] = 0.0f;

#pragma unroll
    for (int ks = 0; ks < 8; ++ks) {
        uint2 b[8];
#pragma unroll
        for (int nt = 0; nt < 8; ++nt)
            b[nt] = WFp[(size_t)((cb0 + nt) * 8 + ks) * 32 + lane];

#pragma unroll
        for (int mt = 0; mt < 2; ++mt) {
            int row = wm * 32 + mt * 16 + lrow;
            uint32_t addr = xsb + (uint32_t)(row * 136 + ks * 16 + kadd) * 2;
            uint32_t a0, a1, a2, a3;
            asm volatile("ldmatrix.sync.aligned.m8n8.x4.shared.b16 {%0,%1,%2,%3}, [%4];"
                         : "=r"(a0), "=r"(a1), "=r"(a2), "=r"(a3) : "r"(addr));
#pragma unroll
            for (int nt = 0; nt < 8; ++nt) {
                asm volatile(
                    "mma.sync.aligned.m16n8k16.row.col.f32.f16.f16.f32 "
                    "{%0,%1,%2,%3}, {%4,%5,%6,%7}, {%8,%9}, {%0,%1,%2,%3};"
                    : "+f"(acc[mt][nt][0]), "+f"(acc[mt][nt][1]),
                      "+f"(acc[mt][nt][2]), "+f"(acc[mt][nt][3])
                    : "r"(a0), "r"(a1), "r"(a2), "r"(a3),
                      "r"(b[nt].x), "r"(b[nt].y));
            }
        }
    }

    const int gp = lane >> 2, tig = lane & 3;
#pragma unroll
    for (int mt = 0; mt < 2; ++mt) {
#pragma unroll
        for (int nt = 0; nt < 8; ++nt) {
            size_t row = row0 + wm * 32 + mt * 16 + gp;
            int col = ny * 256 + wn * 64 + nt * 8 + tig * 2;
            float2 bb = *reinterpret_cast<const float2*>(&bias[col]);
            float2 o0 = make_float2(acc[mt][nt][0] + bb.x, acc[mt][nt][1] + bb.y);
            float2 o1 = make_float2(acc[mt][nt][2] + bb.x, acc[mt][nt][3] + bb.y);
            *reinterpret_cast<float2*>(&XP[row * 512 + col]) = o0;
            *reinterpret_cast<float2*>(&XP[(row + 8) * 512 + col]) = o1;
        }
    }
}

// ---------------- recurrent LSTM layer (K=128, HFMA2, weights in REGISTERS) ----
// One CTA = 8 batches, 512 thr = 128 u x 4 k-groups (32 k each, disjoint).
// Per-thread 128 weight halves (16 uint4 = 64 regs) loaded ONCE before the
// t-loop; inner loop is pure broadcast-LDS + HFMA2.
__global__ void __launch_bounds__(512, 1)
rec_kernel(const float* __restrict__ xp,      // [BT][512] bias included
           const __half* __restrict__ WTh,    // [64][128][8]
           __half* __restrict__ hout,         // [B][T][128] or nullptr
           float* __restrict__ hlast)         // [B][128] or nullptr
{
    extern __shared__ __align__(16) char smd[];
    __half* v = reinterpret_cast<__half*>(smd);                       // [2][8][128]
    float4* part = reinterpret_cast<float4*>(smd + 2 * 8 * NH * 2);   // [8][4][128]

    const uint4* __restrict__ W4 = reinterpret_cast<const uint4*>(WTh);

    const int tid = threadIdx.x;
    const int u   = tid & 127;
    const int kg  = tid >> 7;            // 0..3
    const int b0  = blockIdx.x * 8;
    const int kb0 = kg * 16;             // kk base (16 kk = 32 k)

    // ---- load this thread's weights ONCE (loop-invariant) ----
    uint4 wreg[16];
#pragma unroll
    for (int i = 0; i < 16; ++i)
        wreg[i] = W4[(size_t)(kb0 + i) * NH + u];

    for (int i = tid; i < 1024; i += 512) reinterpret_cast<uint32_t*>(v)[i] = 0u;
    __syncthreads();

    float cst[2] = {0.f, 0.f};
    int p = 0;

    for (int t = 0; t < NT; ++t) {
        // prefetch xp for this thread's 2 cells
        float4 xpv0 = *reinterpret_cast<const float4*>(
            &xp[((size_t)(b0 + kg) * NT + t) * 512 + u * 4]);
        float4 xpv1 = *reinterpret_cast<const float4*>(
            &xp[((size_t)(b0 + kg + 4) * NT + t) * 512 + u * 4]);

        __half2 acch[8][4];
#pragma unroll
        for (int j = 0; j < 8; ++j)
#pragma unroll
            for (int q = 0; q < 4; ++q) acch[j][q] = __float2half2_rn(0.f);

        const __half* vp = v + (size_t)p * 8 * NH;

#pragma unroll
        for (int blk = 0; blk < 4; ++blk) {
            const int kkb = kb0 + blk * 4;
            const __half2* w0 = reinterpret_cast<const __half2*>(&wreg[blk * 4 + 0]);
            const __half2* w1 = reinterpret_cast<const __half2*>(&wreg[blk * 4 + 1]);
            const __half2* w2 = reinterpret_cast<const __half2*>(&wreg[blk * 4 + 2]);
            const __half2* w3 = reinterpret_cast<const __half2*>(&wreg[blk * 4 + 3]);
#pragma unroll
            for (int j = 0; j < 8; ++j) {
                uint4 xv = *reinterpret_cast<const uint4*>(vp + (size_t)j * NH + 2 * kkb);
                const __half2* xpr = reinterpret_cast<const __half2*>(&xv);
#pragma unroll
                for (int q = 0; q < 4; ++q) {
                    acch[j][q] = __hfma2(w0[q], xpr[0], acch[j][q]);
                    acch[j][q] = __hfma2(w1[q], xpr[1], acch[j][q]);
                    acch[j][q] = __hfma2(w2[q], xpr[2], acch[j][q]);
                    acch[j][q] = __hfma2(w3[q], xpr[3], acch[j][q]);
                }
            }
        }

        // single convert + partial write
#pragma unroll
        for (int j = 0; j < 8; ++j) {
            float4 pr;
            pr.x = __low2float(acch[j][0]) + __high2float(acch[j][0]);
            pr.y = __low2float(acch[j][1]) + __high2float(acch[j][1]);
            pr.z = __low2float(acch[j][2]) + __high2float(acch[j][2]);
            pr.w = __low2float(acch[j][3]) + __high2float(acch[j][3]);
            part[((size_t)j * 4 + kg) * NH + u] = pr;
        }
        __syncthreads();

        // reduce + pointwise for 2 cells
        __half* nv = v + (size_t)(1 - p) * 8 * NH;
#pragma unroll
        for (int cell = 0; cell < 2; ++cell) {
            const int j = kg + cell * 4;
            const float4 xpv = cell ? xpv1 : xpv0;
            float4 s0 = part[((size_t)j * 4 + 0) * NH + u];
            float4 s1 = part[((size_t)j * 4 + 1) * NH + u];
            float4 s2 = part[((size_t)j * 4 + 2) * NH + u];
            float4 s3 = part[((size_t)j * 4 + 3) * NH + u];
            float gi = xpv.x + (s0.x + s1.x) + (s2.x + s3.x);
            float gf = xpv.y + (s0.y + s1.y) + (s2.y + s3.y);
            float gg = xpv.z + (s0.z + s1.z) + (s2.z + s3.z);
            float go = xpv.w + (s0.w + s1.w) + (s2.w + s3.w);
            float ii = fast_sig(gi);
            float ff = fast_sig(gf);
            float gz = fast_tanh(gg);
            float oo = fast_sig(go);
            float cn = fmaf(ff, cst[cell], ii * gz);
            cst[cell] = cn;
            float hn = oo * fast_tanh(cn);

            nv[(size_t)j * NH + u] = __float2half(hn);
            if (hout)
                hout[((size_t)(b0 + j) * NT + t) * NH + u] = __float2half(hn);
            if (hlast && t == NT - 1)
                hlast[(b0 + j) * NH + u] = hn;
        }
        __syncthreads();
        p ^= 1;
    }
}

// ---------------- final FC on last timestep of layer 2 ----------------
__global__ void fc_kernel(const float* __restrict__ fc_w,
                          const float* __restrict__ fc_b,
                          float* __restrict__ out)
{
    int b = blockIdx.x;
    int tid = threadIdx.x;
    float p = g_hlast[b * NH + tid] * fc_w[tid];
#pragma unroll
    for (int o = 16; o; o >>= 1) p += __shfl_down_sync(0xffffffffu, p, o);
    __shared__ float ws[4];
    if ((tid & 31) == 0) ws[tid >> 5] = p;
    __syncthreads();
    if (tid == 0) out[b] = ws[0] + ws[1] + ws[2] + ws[3] + fc_b[0];
}

// ---------------- launch ----------------
extern "C" void kernel_launch(void* const* d_in, const int* in_sizes, int n_in,
                              void* d_out, int out_size)
{
    const float* x    = (const float*)d_in[0];
    const float* wih0 = (const float*)d_in[1];
    const float* whh0 = (const float*)d_in[2];
    const float* bih0 = (const float*)d_in[3];
    const float* bhh0 = (const float*)d_in[4];
    const float* wih1 = (const float*)d_in[5];
    const float* whh1 = (const float*)d_in[6];
    const float* bih1 = (const float*)d_in[7];
    const float* bhh1 = (const float*)d_in[8];
    const float* wih2 = (const float*)d_in[9];
    const float* whh2 = (const float*)d_in[10];
    const float* bih2 = (const float*)d_in[11];
    const float* bhh2 = (const float*)d_in[12];
    const float* fcw  = (const float*)d_in[13];
    const float* fcb  = (const float*)d_in[14];
    float* out = (float*)d_out;

    void *ph0, *ph1, *phl, *pxp, *pwt, *pwf, *pbias, *pw0;
    cudaGetSymbolAddress(&ph0, g_h0);
    cudaGetSymbolAddress(&ph1, g_h1);
    cudaGetSymbolAddress(&phl, g_hlast);
    cudaGetSymbolAddress(&pxp, g_xp);
    cudaGetSymbolAddress(&pwt, g_WTh);
    cudaGetSymbolAddress(&pwf, g_WF);
    cudaGetSymbolAddress(&pbias, g_biasxp);
    cudaGetSymbolAddress(&pw0, g_w0p);

    __half* h0   = (__half*)ph0;
    __half* h1   = (__half*)ph1;
    float*  hl   = (float*)phl;
    float*  xp   = (float*)pxp;
    __half* WT   = (__half*)pwt;
    __half* WF   = (__half*)pwf;
    float*  bs   = (float*)pbias;
    float*  w0p  = (float*)pw0;

    const int rec_smem = 2 * 8 * NH * 2 + 8 * 4 * NH * 16;   // 2048 + 65536
    cudaFuncSetAttribute((const void*)rec_kernel,
                         cudaFuncAttributeMaxDynamicSharedMemorySize, rec_smem);

    // prep
    prep_l0_kernel <<<64, 256>>>(wih0, bih0, bhh0, w0p, bs + 0 * 512);
    prep_rec_kernel<<<132, 256>>>(whh0, WT + 0 * 65536);
    prep_mma_kernel<<<132, 256>>>(wih1, bih1, bhh1, WF + 0 * 65536, bs + 1 * 512);
    prep_rec_kernel<<<132, 256>>>(whh1, WT + 1 * 65536);
    prep_mma_kernel<<<132, 256>>>(wih2, bih2, bhh2, WF + 1 * 65536, bs + 2 * 512);
    prep_rec_kernel<<<132, 256>>>(whh2, WT + 2 * 65536);

    // layer 0
    xp0_kernel<<<BT / 128, 512>>>(x, w0p, bs + 0 * 512, xp);
    rec_kernel<<<NB / 8, 512, rec_smem>>>(xp, WT + 0 * 65536, h0, nullptr);

    // layer 1
    {
        dim3 g(BT / 128, 2);
        xp_mma_kernel<<<g, 512>>>(h0, WF + 0 * 65536, bs + 1 * 512, xp);
    }
    rec_kernel<<<NB / 8, 512, rec_smem>>>(xp, WT + 1 * 65536, h1, nullptr);

    // layer 2
    {
        dim3 g(BT / 128, 2);
        xp_mma_kernel<<<g, 512>>>(h1, WF + 1 * 65536, bs + 2 * 512, xp);
    }
    rec_kernel<<<NB / 8, 512, rec_smem>>>(xp, WT + 2 * 65536, nullptr, hl);

    fc_kernel<<<NB, 128>>>(fcw, fcb, out);
}

// round 10
// speedup vs baseline: 1.1649x; 1.1649x over previous
#include <cuda_runtime.h>
#include <cuda_fp16.h>
#include <cstdint>
#include <cstddef>

#define NB 1024
#define NT 512
#define NH 128
#define BT (NB * NT)
#define NBC 7   // batches per rec CTA

// ---------------- scratch (device globals; no runtime allocation) ----------------
__device__ __half g_h0[(size_t)NB * NT * NH];   // layer0 out fp16 [B][T][H]
__device__ __half g_h1[(size_t)NB * NT * NH];   // layer1 out fp16 [B][T][H]
__device__ float  g_hlast[NB * NH];             // layer2 last h (fp32)
__device__ __half g_xph[(size_t)BT * 512];      // x-projection fp16 (reused per layer)
__device__ __half g_WTh[3][64 * NH * 8];        // recurrent w_hh packed [kk][u][8]
__device__ __half g_WF[2][65536];               // mma frag-packed w_ih (layers 1,2)
__device__ float  g_biasxp[3][512];             // per-layer bias (c = u*4+q order)
__device__ float  g_w0p[512 * 8];               // layer0 w_ih packed [c][8] (k<6)

// ---------------- activations ----------------
__device__ __forceinline__ float fast_tanh(float x) {
    float y;
    asm("tanh.approx.f32 %0, %1;" : "=f"(y) : "f"(x));
    return y;
}
__device__ __forceinline__ float fast_sig(float x) {
    return fmaf(0.5f, fast_tanh(0.5f * x), 0.5f);
}
__device__ __forceinline__ uint32_t smem_u32(const void* p) {
    uint32_t a;
    asm("{ .reg .u64 t; cvta.to.shared.u64 t, %1; cvt.u32.u64 %0, t; }" : "=r"(a) : "l"(p));
    return a;
}

// ---------------- prep: recurrent w_hh pack ----------------
__global__ void prep_rec_kernel(const float* __restrict__ w_hh, __half* __restrict__ WT)
{
    for (int idx = blockIdx.x * blockDim.x + threadIdx.x; idx < 64 * NH * 8;
         idx += gridDim.x * blockDim.x) {
        int h8 = idx & 7;
        int u  = (idx >> 3) & 127;
        int kk = idx >> 10;
        int q = h8 >> 1, par = h8 & 1;
        int k = 2 * kk + par;
        WT[idx] = __float2half(w_hh[(q * NH + u) * NH + k]);
    }
}

// ---------------- prep: mma B-frag pack (layers 1,2) + bias ----------------
__global__ void prep_mma_kernel(const float* __restrict__ w_ih,
                                const float* __restrict__ b_ih,
                                const float* __restrict__ b_hh,
                                __half* __restrict__ WF, float* __restrict__ bias)
{
    for (int idx = blockIdx.x * blockDim.x + threadIdx.x; idx < 65536;
         idx += gridDim.x * blockDim.x) {
        int h4   = idx & 3;
        int lane = (idx >> 2) & 31;
        int ks   = (idx >> 7) & 7;
        int cb   = idx >> 10;
        int c = cb * 8 + (lane >> 2);
        int q = c & 3, u = c >> 2;
        int g = q * NH + u;
        int k = ks * 16 + (lane & 3) * 2 + (h4 & 1) + (h4 >> 1) * 8;
        WF[idx] = __float2half(w_ih[g * NH + k]);
    }
    for (int c = blockIdx.x * blockDim.x + threadIdx.x; c < 512;
         c += gridDim.x * blockDim.x) {
        int q = c & 3, u = c >> 2;
        int g = q * NH + u;
        bias[c] = b_ih[g] + b_hh[g];
    }
}

// ---------------- prep: layer0 w_ih pack (K=6) + bias ----------------
__global__ void prep_l0_kernel(const float* __restrict__ w_ih,
                               const float* __restrict__ b_ih,
                               const float* __restrict__ b_hh,
                               float* __restrict__ w0p, float* __restrict__ bias)
{
    for (int idx = blockIdx.x * blockDim.x + threadIdx.x; idx < 512 * 8;
         idx += gridDim.x * blockDim.x) {
        int k = idx & 7, c = idx >> 3;
        int q = c & 3, u = c >> 2;
        int g = q * NH + u;
        w0p[idx] = (k < 6) ? w_ih[g * 6 + k] : 0.0f;
    }
    for (int c = blockIdx.x * blockDim.x + threadIdx.x; c < 512;
         c += gridDim.x * blockDim.x) {
        int q = c & 3, u = c >> 2;
        int g = q * NH + u;
        bias[c] = b_ih[g] + b_hh[g];
    }
}

// ---------------- layer0 x-projection (scalar, K=6) -> fp16 ----------------
__global__ void __launch_bounds__(512, 1)
xp0_kernel(const float* __restrict__ x, const float* __restrict__ w0p,
           const float* __restrict__ bias, __half* __restrict__ XP)
{
    __shared__ __align__(16) float xs[128 * 8];
    const int tid = threadIdx.x;
    const size_t row0 = (size_t)blockIdx.x * 128;

    for (int i = tid; i < 1024; i += 512) {
        int r = i >> 3, k = i & 7;
        xs[i] = (k < 6) ? x[(row0 + r) * 6 + k] : 0.0f;
    }
    __syncthreads();

    const int c = tid;
    float4 w01 = *reinterpret_cast<const float4*>(&w0p[c * 8]);
    float4 w23 = *reinterpret_cast<const float4*>(&w0p[c * 8 + 4]);
    float bc = bias[c];
    for (int r = 0; r < 128; ++r) {
        float4 x01 = *reinterpret_cast<const float4*>(&xs[r * 8]);
        float2 x2  = *reinterpret_cast<const float2*>(&xs[r * 8 + 4]);
        float s = bc;
        s = fmaf(w01.x, x01.x, s);
        s = fmaf(w01.y, x01.y, s);
        s = fmaf(w01.z, x01.z, s);
        s = fmaf(w01.w, x01.w, s);
        s = fmaf(w23.x, x2.x, s);
        s = fmaf(w23.y, x2.y, s);
        XP[(row0 + r) * 512 + c] = __float2half(s);
    }
}

// ---------------- layers 1,2 x-projection via mma.sync -> fp16 ----------------
__global__ void __launch_bounds__(512, 1)
xp_mma_kernel(const __half* __restrict__ X, const __half* __restrict__ WF,
              const float* __restrict__ bias, __half* __restrict__ XP)
{
    __shared__ __align__(16) __half xs[128 * 136];
    const int tid  = threadIdx.x;
    const int wid  = tid >> 5;
    const int lane = tid & 31;
    const size_t row0 = (size_t)blockIdx.x * 128;
    const int ny = blockIdx.y;

    for (int i = tid; i < 2048; i += 512) {
        int r = i >> 4, cvec = i & 15;
        reinterpret_cast<uint4*>(xs)[r * 17 + cvec] =
            reinterpret_cast<const uint4*>(X + (row0 + r) * NH)[cvec];
    }
    __syncthreads();

    const int wm = wid & 3;
    const int wn = wid >> 2;
    const int cb0 = ny * 32 + wn * 8;
    const uint2* __restrict__ WFp = reinterpret_cast<const uint2*>(WF);

    const int lrow = (lane & 7) + ((lane >> 3) & 1) * 8;
    const int kadd = (lane >> 4) * 8;
    const uint32_t xsb = smem_u32(xs);

    float acc[2][8][4];
#pragma unroll
    for (int mt = 0; mt < 2; ++mt)
#pragma unroll
        for (int nt = 0; nt < 8; ++nt)
#pragma unroll
            for (int i = 0; i < 4; ++i) acc[mt][nt][i] = 0.0f;

#pragma unroll
    for (int ks = 0; ks < 8; ++ks) {
        uint2 b[8];
#pragma unroll
        for (int nt = 0; nt < 8; ++nt)
            b[nt] = WFp[(size_t)((cb0 + nt) * 8 + ks) * 32 + lane];

#pragma unroll
        for (int mt = 0; mt < 2; ++mt) {
            int row = wm * 32 + mt * 16 + lrow;
            uint32_t addr = xsb + (uint32_t)(row * 136 + ks * 16 + kadd) * 2;
            uint32_t a0, a1, a2, a3;
            asm volatile("ldmatrix.sync.aligned.m8n8.x4.shared.b16 {%0,%1,%2,%3}, [%4];"
                         : "=r"(a0), "=r"(a1), "=r"(a2), "=r"(a3) : "r"(addr));
#pragma unroll
            for (int nt = 0; nt < 8; ++nt) {
                asm volatile(
                    "mma.sync.aligned.m16n8k16.row.col.f32.f16.f16.f32 "
                    "{%0,%1,%2,%3}, {%4,%5,%6,%7}, {%8,%9}, {%0,%1,%2,%3};"
                    : "+f"(acc[mt][nt][0]), "+f"(acc[mt][nt][1]),
                      "+f"(acc[mt][nt][2]), "+f"(acc[mt][nt][3])
                    : "r"(a0), "r"(a1), "r"(a2), "r"(a3),
                      "r"(b[nt].x), "r"(b[nt].y));
            }
        }
    }

    const int gp = lane >> 2, tig = lane & 3;
#pragma unroll
    for (int mt = 0; mt < 2; ++mt) {
#pragma unroll
        for (int nt = 0; nt < 8; ++nt) {
            size_t row = row0 + wm * 32 + mt * 16 + gp;
            int col = ny * 256 + wn * 64 + nt * 8 + tig * 2;
            float2 bb = *reinterpret_cast<const float2*>(&bias[col]);
            __half2 o0 = __floats2half2_rn(acc[mt][nt][0] + bb.x, acc[mt][nt][1] + bb.y);
            __half2 o1 = __floats2half2_rn(acc[mt][nt][2] + bb.x, acc[mt][nt][3] + bb.y);
            *reinterpret_cast<__half2*>(&XP[row * 512 + col]) = o0;
            *reinterpret_cast<__half2*>(&XP[(row + 8) * 512 + col]) = o1;
        }
    }
}

// ---------------- recurrent LSTM layer (K=128, HFMA2, 7 batches/CTA) ----------
// 147 CTAs; 512 thr = 128 u x 4 k-groups (32 k each, disjoint).
// fp16 accumulate over full group K; single convert; smem partials reduce.
__global__ void __launch_bounds__(512, 1)
rec_kernel(const __half* __restrict__ xp,     // [BT][512] fp16, bias included
           const __half* __restrict__ WTh,    // [64][128][8]
           __half* __restrict__ hout,         // [B][T][128] or nullptr
           float* __restrict__ hlast)         // [B][128] or nullptr
{
    extern __shared__ __align__(16) char smd[];
    __half* v = reinterpret_cast<__half*>(smd);                         // [2][NBC][128]
    float4* part = reinterpret_cast<float4*>(smd + 2 * NBC * NH * 2);   // [NBC][4][128]

    const uint4* __restrict__ W4 = reinterpret_cast<const uint4*>(WTh);

    const int tid = threadIdx.x;
    const int u   = tid & 127;
    const int kg  = tid >> 7;            // 0..3
    const int b0  = blockIdx.x * NBC;
    const int nb  = (NB - b0 < NBC) ? (NB - b0) : NBC;
    const int kb0 = kg * 16;             // kk base (16 kk = 32 k)

    for (int i = tid; i < NBC * NH; i += 512) reinterpret_cast<uint32_t*>(v)[i] = 0u;
    __syncthreads();

    // this thread's cells: j = kg, and j = kg+4 (kg<3)
    const int j0 = kg;
    const int j1 = kg + 4;
    const bool has1 = (j1 < NBC);
    const bool v0 = (j0 < nb);
    const bool v1 = has1 && (j1 < nb);

    float cst[2] = {0.f, 0.f};
    int p = 0;

    for (int t = 0; t < NT; ++t) {
        // prefetch xp (fp16: 4 gates = uint2) for this thread's cells
        uint2 xpu0 = make_uint2(0u, 0u), xpu1 = make_uint2(0u, 0u);
        if (v0)
            xpu0 = *reinterpret_cast<const uint2*>(
                &xp[((size_t)(b0 + j0) * NT + t) * 512 + u * 4]);
        if (v1)
            xpu1 = *reinterpret_cast<const uint2*>(
                &xp[((size_t)(b0 + j1) * NT + t) * 512 + u * 4]);

        __half2 acch[NBC][4];
#pragma unroll
        for (int j = 0; j < NBC; ++j)
#pragma unroll
            for (int q = 0; q < 4; ++q) acch[j][q] = __float2half2_rn(0.f);

        const __half* vp = v + (size_t)p * NBC * NH;

#pragma unroll
        for (int blk = 0; blk < 4; ++blk) {
            const int kkb = kb0 + blk * 4;
            uint4 wv0 = W4[(size_t)(kkb + 0) * NH + u];
            uint4 wv1 = W4[(size_t)(kkb + 1) * NH + u];
            uint4 wv2 = W4[(size_t)(kkb + 2) * NH + u];
            uint4 wv3 = W4[(size_t)(kkb + 3) * NH + u];
            const __half2* w0 = reinterpret_cast<const __half2*>(&wv0);
            const __half2* w1 = reinterpret_cast<const __half2*>(&wv1);
            const __half2* w2 = reinterpret_cast<const __half2*>(&wv2);
            const __half2* w3 = reinterpret_cast<const __half2*>(&wv3);
#pragma unroll
            for (int j = 0; j < NBC; ++j) {
                uint4 xv = *reinterpret_cast<const uint4*>(vp + (size_t)j * NH + 2 * kkb);
                const __half2* xpr = reinterpret_cast<const __half2*>(&xv);
#pragma unroll
                for (int q = 0; q < 4; ++q) {
                    acch[j][q] = __hfma2(w0[q], xpr[0], acch[j][q]);
                    acch[j][q] = __hfma2(w1[q], xpr[1], acch[j][q]);
                    acch[j][q] = __hfma2(w2[q], xpr[2], acch[j][q]);
                    acch[j][q] = __hfma2(w3[q], xpr[3], acch[j][q]);
                }
            }
        }

        // single convert + partial write
#pragma unroll
        for (int j = 0; j < NBC; ++j) {
            float4 pr;
            pr.x = __low2float(acch[j][0]) + __high2float(acch[j][0]);
            pr.y = __low2float(acch[j][1]) + __high2float(acch[j][1]);
            pr.z = __low2float(acch[j][2]) + __high2float(acch[j][2]);
            pr.w = __low2float(acch[j][3]) + __high2float(acch[j][3]);
            part[((size_t)j * 4 + kg) * NH + u] = pr;
        }
        __syncthreads();

        // reduce + pointwise for this thread's cells
        __half* nv = v + (size_t)(1 - p) * NBC * NH;
#pragma unroll
        for (int cell = 0; cell < 2; ++cell) {
            if (cell == 1 && !has1) break;
            const int j = cell ? j1 : j0;
            const uint2 xpu = cell ? xpu1 : xpu0;
            float2 x01 = __half22float2(reinterpret_cast<const __half2*>(&xpu)[0]);
            float2 x23 = __half22float2(reinterpret_cast<const __half2*>(&xpu)[1]);
            float4 s0 = part[((size_t)j * 4 + 0) * NH + u];
            float4 s1 = part[((size_t)j * 4 + 1) * NH + u];
            float4 s2 = part[((size_t)j * 4 + 2) * NH + u];
            float4 s3 = part[((size_t)j * 4 + 3) * NH + u];
            float gi = x01.x + (s0.x + s1.x) + (s2.x + s3.x);
            float gf = x01.y + (s0.y + s1.y) + (s2.y + s3.y);
            float gg = x23.x + (s0.z + s1.z) + (s2.z + s3.z);
            float go = x23.y + (s0.w + s1.w) + (s2.w + s3.w);
            float ii = fast_sig(gi);
            float ff = fast_sig(gf);
            float gz = fast_tanh(gg);
            float oo = fast_sig(go);
            float cn = fmaf(ff, cst[cell], ii * gz);
            cst[cell] = cn;
            float hn = oo * fast_tanh(cn);

            nv[(size_t)j * NH + u] = __float2half(hn);
            const bool vld = cell ? v1 : v0;
            if (hout && vld)
                hout[((size_t)(b0 + j) * NT + t) * NH + u] = __float2half(hn);
            if (hlast && vld && t == NT - 1)
                hlast[(b0 + j) * NH + u] = hn;
        }
        __syncthreads();
        p ^= 1;
    }
}

// ---------------- final FC on last timestep of layer 2 ----------------
__global__ void fc_kernel(const float* __restrict__ fc_w,
                          const float* __restrict__ fc_b,
                          float* __restrict__ out)
{
    int b = blockIdx.x;
    int tid = threadIdx.x;
    float p = g_hlast[b * NH + tid] * fc_w[tid];
#pragma unroll
    for (int o = 16; o; o >>= 1) p += __shfl_down_sync(0xffffffffu, p, o);
    __shared__ float ws[4];
    if ((tid & 31) == 0) ws[tid >> 5] = p;
    __syncthreads();
    if (tid == 0) out[b] = ws[0] + ws[1] + ws[2] + ws[3] + fc_b[0];
}

// ---------------- launch ----------------
extern "C" void kernel_launch(void* const* d_in, const int* in_sizes, int n_in,
                              void* d_out, int out_size)
{
    const float* x    = (const float*)d_in[0];
    const float* wih0 = (const float*)d_in[1];
    const float* whh0 = (const float*)d_in[2];
    const float* bih0 = (const float*)d_in[3];
    const float* bhh0 = (const float*)d_in[4];
    const float* wih1 = (const float*)d_in[5];
    const float* whh1 = (const float*)d_in[6];
    const float* bih1 = (const float*)d_in[7];
    const float* bhh1 = (const float*)d_in[8];
    const float* wih2 = (const float*)d_in[9];
    const float* whh2 = (const float*)d_in[10];
    const float* bih2 = (const float*)d_in[11];
    const float* bhh2 = (const float*)d_in[12];
    const float* fcw  = (const float*)d_in[13];
    const float* fcb  = (const float*)d_in[14];
    float* out = (float*)d_out;

    void *ph0, *ph1, *phl, *pxp, *pwt, *pwf, *pbias, *pw0;
    cudaGetSymbolAddress(&ph0, g_h0);
    cudaGetSymbolAddress(&ph1, g_h1);
    cudaGetSymbolAddress(&phl, g_hlast);
    cudaGetSymbolAddress(&pxp, g_xph);
    cudaGetSymbolAddress(&pwt, g_WTh);
    cudaGetSymbolAddress(&pwf, g_WF);
    cudaGetSymbolAddress(&pbias, g_biasxp);
    cudaGetSymbolAddress(&pw0, g_w0p);

    __half* h0   = (__half*)ph0;
    __half* h1   = (__half*)ph1;
    float*  hl   = (float*)phl;
    __half* xp   = (__half*)pxp;
    __half* WT   = (__half*)pwt;
    __half* WF   = (__half*)pwf;
    float*  bs   = (float*)pbias;
    float*  w0p  = (float*)pw0;

    const int rec_smem = 2 * NBC * NH * 2 + NBC * 4 * NH * 16;   // 3584 + 57344
    cudaFuncSetAttribute((const void*)rec_kernel,
                         cudaFuncAttributeMaxDynamicSharedMemorySize, rec_smem);
    const int rec_grid = (NB + NBC - 1) / NBC;   // 147

    // prep
    prep_l0_kernel <<<64, 256>>>(wih0, bih0, bhh0, w0p, bs + 0 * 512);
    prep_rec_kernel<<<132, 256>>>(whh0, WT + 0 * 65536);
    prep_mma_kernel<<<132, 256>>>(wih1, bih1, bhh1, WF + 0 * 65536, bs + 1 * 512);
    prep_rec_kernel<<<132, 256>>>(whh1, WT + 1 * 65536);
    prep_mma_kernel<<<132, 256>>>(wih2, bih2, bhh2, WF + 1 * 65536, bs + 2 * 512);
    prep_rec_kernel<<<132, 256>>>(whh2, WT + 2 * 65536);

    // layer 0
    xp0_kernel<<<BT / 128, 512>>>(x, w0p, bs + 0 * 512, xp);
    rec_kernel<<<rec_grid, 512, rec_smem>>>(xp, WT + 0 * 65536, h0, nullptr);

    // layer 1
    {
        dim3 g(BT / 128, 2);
        xp_mma_kernel<<<g, 512>>>(h0, WF + 0 * 65536, bs + 1 * 512, xp);
    }
    rec_kernel<<<rec_grid, 512, rec_smem>>>(xp, WT + 1 * 65536, h1, nullptr);

    // layer 2
    {
        dim3 g(BT / 128, 2);
        xp_mma_kernel<<<g, 512>>>(h1, WF + 1 * 65536, bs + 2 * 512, xp);
    }
    rec_kernel<<<rec_grid, 512, rec_smem>>>(xp, WT + 2 * 65536, nullptr, hl);

    fc_kernel<<<NB, 128>>>(fcw, fcb, out);
}

// round 11
// speedup vs baseline: 2.4165x; 2.0744x over previous
#include <cuda_runtime.h>
#include <cuda_fp16.h>
#include <cstdint>
#include <cstddef>

#define NB 1024
#define NT 512
#define NH 128
#define BT (NB * NT)
#define NBC 7   // batches per rec CTA

// ---------------- scratch (device globals; no runtime allocation) ----------------
__device__ __half g_h0[(size_t)NB * NT * NH];   // layer0 out fp16 [B][T][H]
__device__ __half g_h1[(size_t)NB * NT * NH];   // layer1 out fp16 [B][T][H]
__device__ float  g_hlast[NB * NH];             // layer2 last h (fp32)
__device__ __half g_xph[(size_t)BT * 512];      // x-projection fp16 (reused per layer)
__device__ __half g_WF[2][65536];               // mma frag-packed w_ih (layers 1,2)
__device__ __half g_WR[3][65536];               // mma frag-packed w_hh (all layers)
__device__ float  g_biasxp[3][512];             // per-layer bias (c = u*4+q order)
__device__ float  g_w0p[512 * 8];               // layer0 w_ih packed [c][8] (k<6)

// ---------------- activations ----------------
__device__ __forceinline__ float fast_tanh(float x) {
    float y;
    asm("tanh.approx.f32 %0, %1;" : "=f"(y) : "f"(x));
    return y;
}
__device__ __forceinline__ float fast_sig(float x) {
    return fmaf(0.5f, fast_tanh(0.5f * x), 0.5f);
}
__device__ __forceinline__ uint32_t smem_u32(const void* p) {
    uint32_t a;
    asm("{ .reg .u64 t; cvta.to.shared.u64 t, %1; cvt.u32.u64 %0, t; }" : "=r"(a) : "l"(p));
    return a;
}

// ---------------- prep: mma B-frag pack for a [512,128] matrix + bias ----------
// WF flat half idx: h4 = idx&3, lane = (idx>>2)&31, ks = (idx>>7)&7, cb = idx>>10
// c = cb*8 + lane/4; k = ks*16 + (lane&3)*2 + (h4&1) + (h4>>1)*8; val = W[g][k]
__global__ void prep_mma_kernel(const float* __restrict__ W,
                                const float* __restrict__ b_ih,
                                const float* __restrict__ b_hh,
                                __half* __restrict__ WF, float* __restrict__ bias)
{
    for (int idx = blockIdx.x * blockDim.x + threadIdx.x; idx < 65536;
         idx += gridDim.x * blockDim.x) {
        int h4   = idx & 3;
        int lane = (idx >> 2) & 31;
        int ks   = (idx >> 7) & 7;
        int cb   = idx >> 10;
        int c = cb * 8 + (lane >> 2);
        int q = c & 3, u = c >> 2;
        int g = q * NH + u;
        int k = ks * 16 + (lane & 3) * 2 + (h4 & 1) + (h4 >> 1) * 8;
        WF[idx] = __float2half(W[g * NH + k]);
    }
    for (int c = blockIdx.x * blockDim.x + threadIdx.x; c < 512;
         c += gridDim.x * blockDim.x) {
        int q = c & 3, u = c >> 2;
        int g = q * NH + u;
        bias[c] = b_ih[g] + b_hh[g];
    }
}

// ---------------- prep: layer0 w_ih pack (K=6) + bias ----------------
__global__ void prep_l0_kernel(const float* __restrict__ w_ih,
                               const float* __restrict__ b_ih,
                               const float* __restrict__ b_hh,
                               float* __restrict__ w0p, float* __restrict__ bias)
{
    for (int idx = blockIdx.x * blockDim.x + threadIdx.x; idx < 512 * 8;
         idx += gridDim.x * blockDim.x) {
        int k = idx & 7, c = idx >> 3;
        int q = c & 3, u = c >> 2;
        int g = q * NH + u;
        w0p[idx] = (k < 6) ? w_ih[g * 6 + k] : 0.0f;
    }
    for (int c = blockIdx.x * blockDim.x + threadIdx.x; c < 512;
         c += gridDim.x * blockDim.x) {
        int q = c & 3, u = c >> 2;
        int g = q * NH + u;
        bias[c] = b_ih[g] + b_hh[g];
    }
}

// ---------------- layer0 x-projection (scalar, K=6) -> fp16 ----------------
__global__ void __launch_bounds__(512, 1)
xp0_kernel(const float* __restrict__ x, const float* __restrict__ w0p,
           const float* __restrict__ bias, __half* __restrict__ XP)
{
    __shared__ __align__(16) float xs[128 * 8];
    const int tid = threadIdx.x;
    const size_t row0 = (size_t)blockIdx.x * 128;

    for (int i = tid; i < 1024; i += 512) {
        int r = i >> 3, k = i & 7;
        xs[i] = (k < 6) ? x[(row0 + r) * 6 + k] : 0.0f;
    }
    __syncthreads();

    const int c = tid;
    float4 w01 = *reinterpret_cast<const float4*>(&w0p[c * 8]);
    float4 w23 = *reinterpret_cast<const float4*>(&w0p[c * 8 + 4]);
    float bc = bias[c];
    for (int r = 0; r < 128; ++r) {
        float4 x01 = *reinterpret_cast<const float4*>(&xs[r * 8]);
        float2 x2  = *reinterpret_cast<const float2*>(&xs[r * 8 + 4]);
        float s = bc;
        s = fmaf(w01.x, x01.x, s);
        s = fmaf(w01.y, x01.y, s);
        s = fmaf(w01.z, x01.z, s);
        s = fmaf(w01.w, x01.w, s);
        s = fmaf(w23.x, x2.x, s);
        s = fmaf(w23.y, x2.y, s);
        XP[(row0 + r) * 512 + c] = __float2half(s);
    }
}

// ---------------- layers 1,2 x-projection via mma.sync -> fp16 ----------------
__global__ void __launch_bounds__(512, 1)
xp_mma_kernel(const __half* __restrict__ X, const __half* __restrict__ WF,
              const float* __restrict__ bias, __half* __restrict__ XP)
{
    __shared__ __align__(16) __half xs[128 * 136];
    const int tid  = threadIdx.x;
    const int wid  = tid >> 5;
    const int lane = tid & 31;
    const size_t row0 = (size_t)blockIdx.x * 128;
    const int ny = blockIdx.y;

    for (int i = tid; i < 2048; i += 512) {
        int r = i >> 4, cvec = i & 15;
        reinterpret_cast<uint4*>(xs)[r * 17 + cvec] =
            reinterpret_cast<const uint4*>(X + (row0 + r) * NH)[cvec];
    }
    __syncthreads();

    const int wm = wid & 3;
    const int wn = wid >> 2;
    const int cb0 = ny * 32 + wn * 8;
    const uint2* __restrict__ WFp = reinterpret_cast<const uint2*>(WF);

    const int lrow = (lane & 7) + ((lane >> 3) & 1) * 8;
    const int kadd = (lane >> 4) * 8;
    const uint32_t xsb = smem_u32(xs);

    float acc[2][8][4];
#pragma unroll
    for (int mt = 0; mt < 2; ++mt)
#pragma unroll
        for (int nt = 0; nt < 8; ++nt)
#pragma unroll
            for (int i = 0; i < 4; ++i) acc[mt][nt][i] = 0.0f;

#pragma unroll
    for (int ks = 0; ks < 8; ++ks) {
        uint2 b[8];
#pragma unroll
        for (int nt = 0; nt < 8; ++nt)
            b[nt] = WFp[(size_t)((cb0 + nt) * 8 + ks) * 32 + lane];

#pragma unroll
        for (int mt = 0; mt < 2; ++mt) {
            int row = wm * 32 + mt * 16 + lrow;
            uint32_t addr = xsb + (uint32_t)(row * 136 + ks * 16 + kadd) * 2;
            uint32_t a0, a1, a2, a3;
            asm volatile("ldmatrix.sync.aligned.m8n8.x4.shared.b16 {%0,%1,%2,%3}, [%4];"
                         : "=r"(a0), "=r"(a1), "=r"(a2), "=r"(a3) : "r"(addr));
#pragma unroll
            for (int nt = 0; nt < 8; ++nt) {
                asm volatile(
                    "mma.sync.aligned.m16n8k16.row.col.f32.f16.f16.f32 "
                    "{%0,%1,%2,%3}, {%4,%5,%6,%7}, {%8,%9}, {%0,%1,%2,%3};"
                    : "+f"(acc[mt][nt][0]), "+f"(acc[mt][nt][1]),
                      "+f"(acc[mt][nt][2]), "+f"(acc[mt][nt][3])
                    : "r"(a0), "r"(a1), "r"(a2), "r"(a3),
                      "r"(b[nt].x), "r"(b[nt].y));
            }
        }
    }

    const int gp = lane >> 2, tig = lane & 3;
#pragma unroll
    for (int mt = 0; mt < 2; ++mt) {
#pragma unroll
        for (int nt = 0; nt < 8; ++nt) {
            size_t row = row0 + wm * 32 + mt * 16 + gp;
            int col = ny * 256 + wn * 64 + nt * 8 + tig * 2;
            float2 bb = *reinterpret_cast<const float2*>(&bias[col]);
            __half2 o0 = __floats2half2_rn(acc[mt][nt][0] + bb.x, acc[mt][nt][1] + bb.y);
            __half2 o1 = __floats2half2_rn(acc[mt][nt][2] + bb.x, acc[mt][nt][3] + bb.y);
            *reinterpret_cast<__half2*>(&XP[row * 512 + col]) = o0;
            *reinterpret_cast<__half2*>(&XP[(row + 8) * 512 + col]) = o1;
        }
    }
}

// ---------------- recurrent LSTM layer via mma.sync ----------------
// 147 CTAs x 512 thr; CTA = 7 batches (padded to one m16 tile).
// Per step: each warp owns 32 gate-cols (4 n8 tiles), full K=128 (8 k-steps):
// 8 ldmatrix.x4 + 32 mma, fp32 acc -> fp16 D smem -> gather gate quads + xp,
// pointwise, h into A tile. B-frags (w_hh) loop-invariant in registers.
__global__ void __launch_bounds__(512, 1)
rec_mma_kernel(const __half* __restrict__ xp,     // [BT][512] fp16, bias included
               const __half* __restrict__ WR,     // frag-packed w_hh
               __half* __restrict__ hout,         // [B][T][128] or nullptr
               float* __restrict__ hlast)         // [B][128] or nullptr
{
    __shared__ __align__(16) __half A[16 * 136];    // h tile, rows>=NBC stay 0
    __shared__ __align__(16) __half Dsm[8 * 520];   // gate pre-acts (rows 0..7)

    const int tid  = threadIdx.x;
    const int wid  = tid >> 5;
    const int lane = tid & 31;
    const int b0   = blockIdx.x * NBC;
    const int nb   = (NB - b0 < NBC) ? (NB - b0) : NBC;

    // gather-role ids
    const int u  = tid & 127;
    const int kg = tid >> 7;
    const int j0 = kg;
    const int j1 = kg + 4;
    const bool has1 = (j1 < NBC);
    const bool v0 = (j0 < nb);
    const bool v1 = has1 && (j1 < nb);

    // mma-role: warp owns cols [wid*32, wid*32+32)
    const int cb0 = wid * 4;
    const uint2* __restrict__ WRp = reinterpret_cast<const uint2*>(WR);

    // loop-invariant B fragments (w_hh) -> 64 regs
    uint2 breg[4][8];
#pragma unroll
    for (int nt = 0; nt < 4; ++nt)
#pragma unroll
        for (int ks = 0; ks < 8; ++ks)
            breg[nt][ks] = WRp[(size_t)((cb0 + nt) * 8 + ks) * 32 + lane];

    // zero A tile (h starts at 0; pad rows stay 0)
    for (int i = tid; i < 16 * 136 / 2; i += 512)
        reinterpret_cast<uint32_t*>(A)[i] = 0u;
    __syncthreads();

    const int lrow = (lane & 7) + ((lane >> 3) & 1) * 8;
    const int kadd = (lane >> 4) * 8;
    const uint32_t Ab = smem_u32(A);
    const int gp = lane >> 2, tig = lane & 3;

    float cst[2] = {0.f, 0.f};

    for (int t = 0; t < NT; ++t) {
        // prefetch xp (fp16 gate quad = uint2) for this thread's cells
        uint2 xpu0 = make_uint2(0u, 0u), xpu1 = make_uint2(0u, 0u);
        if (v0)
            xpu0 = *reinterpret_cast<const uint2*>(
                &xp[((size_t)(b0 + j0) * NT + t) * 512 + u * 4]);
        if (v1)
            xpu1 = *reinterpret_cast<const uint2*>(
                &xp[((size_t)(b0 + j1) * NT + t) * 512 + u * 4]);

        // ---- W_hh * h via mma.sync ----
        float acc[4][4];
#pragma unroll
        for (int nt = 0; nt < 4; ++nt)
#pragma unroll
            for (int i = 0; i < 4; ++i) acc[nt][i] = 0.0f;

#pragma unroll
        for (int ks = 0; ks < 8; ++ks) {
            uint32_t addr = Ab + (uint32_t)(lrow * 136 + ks * 16 + kadd) * 2;
            uint32_t a0, a1, a2, a3;
            asm volatile("ldmatrix.sync.aligned.m8n8.x4.shared.b16 {%0,%1,%2,%3}, [%4];"
                         : "=r"(a0), "=r"(a1), "=r"(a2), "=r"(a3) : "r"(addr));
#pragma unroll
            for (int nt = 0; nt < 4; ++nt) {
                asm volatile(
                    "mma.sync.aligned.m16n8k16.row.col.f32.f16.f16.f32 "
                    "{%0,%1,%2,%3}, {%4,%5,%6,%7}, {%8,%9}, {%0,%1,%2,%3};"
                    : "+f"(acc[nt][0]), "+f"(acc[nt][1]),
                      "+f"(acc[nt][2]), "+f"(acc[nt][3])
                    : "r"(a0), "r"(a1), "r"(a2), "r"(a3),
                      "r"(breg[nt][ks].x), "r"(breg[nt][ks].y));
            }
        }

        // ---- store D rows 0..7 (row gp) to smem as fp16 ----
#pragma unroll
        for (int nt = 0; nt < 4; ++nt) {
            __half2 d = __floats2half2_rn(acc[nt][0], acc[nt][1]);
            *reinterpret_cast<__half2*>(&Dsm[gp * 520 + (cb0 + nt) * 8 + tig * 2]) = d;
        }
        __syncthreads();

        // ---- gather gate quads + xp, pointwise, write h into A ----
#pragma unroll
        for (int cell = 0; cell < 2; ++cell) {
            if (cell == 1 && !has1) break;
            const int j = cell ? j1 : j0;
            const uint2 xpu = cell ? xpu1 : xpu0;
            uint2 d2 = *reinterpret_cast<const uint2*>(&Dsm[j * 520 + u * 4]);
            float2 r01 = __half22float2(reinterpret_cast<const __half2*>(&d2)[0]);
            float2 r23 = __half22float2(reinterpret_cast<const __half2*>(&d2)[1]);
            float2 x01 = __half22float2(reinterpret_cast<const __half2*>(&xpu)[0]);
            float2 x23 = __half22float2(reinterpret_cast<const __half2*>(&xpu)[1]);
            float gi = r01.x + x01.x;
            float gf = r01.y + x01.y;
            float gg = r23.x + x23.x;
            float go = r23.y + x23.y;
            float ii = fast_sig(gi);
            float ff = fast_sig(gf);
            float gz = fast_tanh(gg);
            float oo = fast_sig(go);
            float cn = fmaf(ff, cst[cell], ii * gz);
            cst[cell] = cn;
            float hn = oo * fast_tanh(cn);
            __half hn16 = __float2half(hn);

            A[j * 136 + u] = hn16;
            const bool vld = cell ? v1 : v0;
            if (hout && vld)
                hout[((size_t)(b0 + j) * NT + t) * NH + u] = hn16;
            if (hlast && vld && t == NT - 1)
                hlast[(b0 + j) * NH + u] = hn;
        }
        __syncthreads();
    }
}

// ---------------- final FC on last timestep of layer 2 ----------------
__global__ void fc_kernel(const float* __restrict__ fc_w,
                          const float* __restrict__ fc_b,
                          float* __restrict__ out)
{
    int b = blockIdx.x;
    int tid = threadIdx.x;
    float p = g_hlast[b * NH + tid] * fc_w[tid];
#pragma unroll
    for (int o = 16; o; o >>= 1) p += __shfl_down_sync(0xffffffffu, p, o);
    __shared__ float ws[4];
    if ((tid & 31) == 0) ws[tid >> 5] = p;
    __syncthreads();
    if (tid == 0) out[b] = ws[0] + ws[1] + ws[2] + ws[3] + fc_b[0];
}

// ---------------- launch ----------------
extern "C" void kernel_launch(void* const* d_in, const int* in_sizes, int n_in,
                              void* d_out, int out_size)
{
    const float* x    = (const float*)d_in[0];
    const float* wih0 = (const float*)d_in[1];
    const float* whh0 = (const float*)d_in[2];
    const float* bih0 = (const float*)d_in[3];
    const float* bhh0 = (const float*)d_in[4];
    const float* wih1 = (const float*)d_in[5];
    const float* whh1 = (const float*)d_in[6];
    const float* bih1 = (const float*)d_in[7];
    const float* bhh1 = (const float*)d_in[8];
    const float* wih2 = (const float*)d_in[9];
    const float* whh2 = (const float*)d_in[10];
    const float* bih2 = (const float*)d_in[11];
    const float* bhh2 = (const float*)d_in[12];
    const float* fcw  = (const float*)d_in[13];
    const float* fcb  = (const float*)d_in[14];
    float* out = (float*)d_out;

    void *ph0, *ph1, *phl, *pxp, *pwf, *pwr, *pbias, *pw0;
    cudaGetSymbolAddress(&ph0, g_h0);
    cudaGetSymbolAddress(&ph1, g_h1);
    cudaGetSymbolAddress(&phl, g_hlast);
    cudaGetSymbolAddress(&pxp, g_xph);
    cudaGetSymbolAddress(&pwf, g_WF);
    cudaGetSymbolAddress(&pwr, g_WR);
    cudaGetSymbolAddress(&pbias, g_biasxp);
    cudaGetSymbolAddress(&pw0, g_w0p);

    __half* h0   = (__half*)ph0;
    __half* h1   = (__half*)ph1;
    float*  hl   = (float*)phl;
    __half* xp   = (__half*)pxp;
    __half* WF   = (__half*)pwf;
    __half* WR   = (__half*)pwr;
    float*  bs   = (float*)pbias;
    float*  w0p  = (float*)pw0;

    const int rec_grid = (NB + NBC - 1) / NBC;   // 147

    // prep: layer0 x-proj pack; frag packs for w_ih (L1,2) and w_hh (all)
    prep_l0_kernel <<<64, 256>>>(wih0, bih0, bhh0, w0p, bs + 0 * 512);
    prep_mma_kernel<<<132, 256>>>(whh0, bih0, bhh0, WR + 0 * 65536, bs + 0 * 512);
    prep_mma_kernel<<<132, 256>>>(wih1, bih1, bhh1, WF + 0 * 65536, bs + 1 * 512);
    prep_mma_kernel<<<132, 256>>>(whh1, bih1, bhh1, WR + 1 * 65536, bs + 1 * 512);
    prep_mma_kernel<<<132, 256>>>(wih2, bih2, bhh2, WF + 1 * 65536, bs + 2 * 512);
    prep_mma_kernel<<<132, 256>>>(whh2, bih2, bhh2, WR + 2 * 65536, bs + 2 * 512);

    // layer 0
    xp0_kernel<<<BT / 128, 512>>>(x, w0p, bs + 0 * 512, xp);
    rec_mma_kernel<<<rec_grid, 512>>>(xp, WR + 0 * 65536, h0, nullptr);

    // layer 1
    {
        dim3 g(BT / 128, 2);
        xp_mma_kernel<<<g, 512>>>(h0, WF + 0 * 65536, bs + 1 * 512, xp);
    }
    rec_mma_kernel<<<rec_grid, 512>>>(xp, WR + 1 * 65536, h1, nullptr);

    // layer 2
    {
        dim3 g(BT / 128, 2);
        xp_mma_kernel<<<g, 512>>>(h1, WF + 1 * 65536, bs + 2 * 512, xp);
    }
    rec_mma_kernel<<<rec_grid, 512>>>(xp, WR + 2 * 65536, nullptr, hl);

    fc_kernel<<<NB, 128>>>(fcw, fcb, out);
}